// round 17
// baseline (speedup 1.0000x reference)
#include <cuda_runtime.h>

// LinearSpline: per-channel slope-clipped linear spline activation, fused.
// x: [32, 64, 128, 128] f32, coefficients_vect: [64*51] f32, scaling: [64] f32.
//
// 64-thread blocks (R16-proven granularity), grid 32768, 4 front-batched
// LDG.128/thread. NEW: NO block barrier — each of the 2 warps builds its own
// private {c0, slope} table via shfl scan (only __syncwarp orders STS->LDS),
// and the scale broadcasts through registers. Warps are fully independent;
// the last block-start serialization (sibling waiting on warp 0's scan) gone.

#define NCH   64
#define SZ    51
#define HALFI 25                               // SIZE // 2
#define GRID_D   (2.0 * 1.0 / (SZ - 1))        // 0.04 (double, matches python)
#define GRID_F   ((float)GRID_D)
#define TLO   (-25.0f)                         // clamp bounds in t = xs*25 domain
#define THI   ( 24.0f)

#define THREADS   64
#define NWARPS    (THREADS / 32)
#define BLOCK_V4  256                          // 1024 elems / 4

__global__ void __launch_bounds__(THREADS, 24)  // reg cap 42 (compiles at ~40)
spline_fused_kernel(const float4* __restrict__ x,
                    const float*  __restrict__ coeff,
                    const float*  __restrict__ scale,
                    float4* __restrict__ out) {
    __shared__ float2 tabs[NWARPS][SZ - 1];    // per-warp private {c0, slope}

    int lane = threadIdx.x & 31;
    int wid  = threadIdx.x >> 5;
    float2* __restrict__ mytab = tabs[wid];

    // block covers 1024 elems; plane = 16384; c = (b>>4) & 63
    int c = (blockIdx.x >> 4) & (NCH - 1);
    int base = blockIdx.x * BLOCK_V4 + threadIdx.x;

    // ---- ALL loads first: whole block's read traffic in flight -------------
    float4 v0 = __ldcs(x + base);
    float4 v1 = __ldcs(x + base + THREADS);
    float4 v2 = __ldcs(x + base + THREADS * 2);
    float4 v3 = __ldcs(x + base + THREADS * 3);

    // ---- per-warp table build: shfl parallel scan (no block barrier) -------
    {
        const float* cs = coeff + c * SZ;
        float a  = (2 * lane     <= 50) ? __ldg(cs + 2 * lane)     : 0.0f; // cs[2l]
        float bb = (2 * lane + 1 <= 50) ? __ldg(cs + 2 * lane + 1) : 0.0f; // cs[2l+1]
        float a_next = __shfl_down_sync(0xffffffff, a, 1);                 // cs[2l+2]
        float s_even = fminf(fmaxf(bb - a,      0.0f), GRID_F);  // slope[2l]
        float s_odd  = fminf(fmaxf(a_next - bb, 0.0f), GRID_F);  // slope[2l+1]
        float p = (lane <= 24) ? (s_even + s_odd) : 0.0f;
        float P = p;                                             // inclusive scan
#pragma unroll
        for (int off = 1; off < 32; off <<= 1) {
            float t = __shfl_up_sync(0xffffffff, P, off);
            if (lane >= off) P += t;
        }
        float v_even = P - p;                  // vals[2l]  (exclusive)
        float v_odd  = v_even + s_even;        // vals[2l+1]
        float mid = __shfl_sync(0xffffffff, v_odd, 12);   // vals[25]
        if (lane <= 24) {
            mytab[2 * lane]     = make_float2(v_even - mid, s_even);
            mytab[2 * lane + 1] = make_float2(v_odd  - mid, s_odd);
        }
    }
    // scale broadcast in registers (no smem, no block sync)
    float s = __shfl_sync(0xffffffff,
                          (lane == 0) ? __ldg(scale + c) : 0.0f, 0);
    float s25   = s * 25.0f;                   // fold 1/GRID into the scale
    float inv_s = __fdividef(1.0f, s);
    __syncwarp();                              // order STS -> LDS within warp

    // ---- evaluate + store, pairwise (frees v-regs as we go) ----------------
    {
        float xin0[4] = {v0.x, v0.y, v0.z, v0.w};
        float xin1[4] = {v1.x, v1.y, v1.z, v1.w};
        float r0[4], r1[4];
#pragma unroll
        for (int k = 0; k < 4; ++k) {
            float t  = xin0[k] * s25;                      // = xs / GRID
            float tc = fminf(fmaxf(t, TLO), THI);          // clamp in t-domain
            float fl = floorf(tc);                         // [-25, 24]
            float fr = t - fl;                             // frac from UNCLAMPED t
            int idx  = HALFI + (int)fl;                    // [0, 49]
            float2 p = mytab[idx];                         // LDS.64 gather
            r0[k] = fmaf(fr, p.y, p.x) * inv_s;
        }
#pragma unroll
        for (int k = 0; k < 4; ++k) {
            float t  = xin1[k] * s25;
            float tc = fminf(fmaxf(t, TLO), THI);
            float fl = floorf(tc);
            float fr = t - fl;
            int idx  = HALFI + (int)fl;
            float2 p = mytab[idx];
            r1[k] = fmaf(fr, p.y, p.x) * inv_s;
        }
        __stcs(out + base,           make_float4(r0[0], r0[1], r0[2], r0[3]));
        __stcs(out + base + THREADS, make_float4(r1[0], r1[1], r1[2], r1[3]));
    }
    {
        float xin0[4] = {v2.x, v2.y, v2.z, v2.w};
        float xin1[4] = {v3.x, v3.y, v3.z, v3.w};
        float r0[4], r1[4];
#pragma unroll
        for (int k = 0; k < 4; ++k) {
            float t  = xin0[k] * s25;
            float tc = fminf(fmaxf(t, TLO), THI);
            float fl = floorf(tc);
            float fr = t - fl;
            int idx  = HALFI + (int)fl;
            float2 p = mytab[idx];
            r0[k] = fmaf(fr, p.y, p.x) * inv_s;
        }
#pragma unroll
        for (int k = 0; k < 4; ++k) {
            float t  = xin1[k] * s25;
            float tc = fminf(fmaxf(t, TLO), THI);
            float fl = floorf(tc);
            float fr = t - fl;
            int idx  = HALFI + (int)fl;
            float2 p = mytab[idx];
            r1[k] = fmaf(fr, p.y, p.x) * inv_s;
        }
        __stcs(out + base + THREADS * 2, make_float4(r0[0], r0[1], r0[2], r0[3]));
        __stcs(out + base + THREADS * 3, make_float4(r1[0], r1[1], r1[2], r1[3]));
    }
}

extern "C" void kernel_launch(void* const* d_in, const int* in_sizes, int n_in,
                              void* d_out, int out_size) {
    const float* x     = (const float*)d_in[0];
    const float* coeff = (const float*)d_in[1];
    const float* scl   = (const float*)d_in[2];
    float* out = (float*)d_out;

    int n  = out_size;                 // 33554432
    int blocks = n / (BLOCK_V4 * 4);   // 32768
    spline_fused_kernel<<<blocks, THREADS>>>((const float4*)x, coeff, scl,
                                             (float4*)out);
}